// round 11
// baseline (speedup 1.0000x reference)
#include <cuda_runtime.h>
#include <cuda_bf16.h>
#include <cstdint>

#define N_SAMPLES 100000
#define NUM_EDGES 1600000
#define D_FEAT    128
#define EPS_F     1e-8f
#define LAMBDA_REG 1.0
#define GAMMA_C    0.1
#define FULLMASK   0xFFFFFFFFu
#define SLOT_CAP   64
#define NBIN       2048

struct __align__(8) Pk { float nv; int row; };

// ---------------- device scratch (no allocations allowed) ----------------
__device__ int4         g_rec[(size_t)N_SAMPLES * SLOT_CAP];    // 102.4 MB
__device__ Pk           g_packed[(size_t)N_SAMPLES * SLOT_CAP]; // 51.2 MB
__device__ uint2        g_Zh[(size_t)N_SAMPLES * D_FEAT / 4];   // 25.6 MB bf16 Z
__device__ int          g_cnt[N_SAMPLES];
__device__ double       g_recon_sum;
__device__ double       g_reg_sum;
__device__ double       g_block_sum;
__device__ unsigned int g_hist[2][NBIN];
__device__ unsigned int g_prefix[2];
__device__ unsigned int g_rank[2];
__device__ unsigned int g_tick[4];
__device__ int          g_is64;

// ---------------- helpers ----------------
__device__ __forceinline__ double blockReduceD(double v) {
    __shared__ double sh[32];
    #pragma unroll
    for (int o = 16; o; o >>= 1) v += __shfl_down_sync(FULLMASK, v, o);
    int lane = threadIdx.x & 31, w = threadIdx.x >> 5;
    if (lane == 0) sh[w] = v;
    __syncthreads();
    int nw = blockDim.x >> 5;
    v = (threadIdx.x < (unsigned)nw) ? sh[threadIdx.x] : 0.0;
    if (w == 0) {
        #pragma unroll
        for (int o = 16; o; o >>= 1) v += __shfl_down_sync(FULLMASK, v, o);
    }
    return v;
}

// Block-parallel walk of the 2048-bin histograms (last block of a pass).
// Requires blockDim.x == 256.
__device__ void walk2048_and_reset(int shift, bool pass0) {
    __shared__ unsigned s_part[256];
    __shared__ unsigned s_ws[8];
    __shared__ unsigned s_found, s_res;
    int t = threadIdx.x, lane = t & 31, w = t >> 5;
    for (int s = 0; s < 2; s++) {
        const unsigned* h = pass0 ? g_hist[0] : g_hist[s];
        unsigned loc[8], psum = 0;
        #pragma unroll
        for (int q = 0; q < 8; q++) { loc[q] = h[t * 8 + q]; psum += loc[q]; }
        s_part[t] = psum;
        __syncthreads();
        unsigned v = s_part[t];
        #pragma unroll
        for (int o = 1; o < 32; o <<= 1) {
            unsigned x = __shfl_up_sync(FULLMASK, v, o);
            if (lane >= o) v += x;
        }
        if (lane == 31) s_ws[w] = v;
        __syncthreads();
        if (w == 0) {
            unsigned x = (lane < 8) ? s_ws[lane] : 0;
            #pragma unroll
            for (int o = 1; o < 8; o <<= 1) {
                unsigned y = __shfl_up_sync(FULLMASK, x, o);
                if (lane >= o) x += y;
            }
            if (lane < 8) s_ws[lane] = x;
        }
        __syncthreads();
        unsigned incl = v + (w ? s_ws[w - 1] : 0);
        unsigned cum = incl - psum;
        unsigned r = g_rank[s];
        #pragma unroll
        for (int q = 0; q < 8; q++) {
            if (cum <= r && r < cum + loc[q]) {
                s_found = (unsigned)(t * 8 + q);
                s_res = r - cum;
            }
            cum += loc[q];
        }
        __syncthreads();
        if (t == 0) {
            g_prefix[s] |= s_found << shift;
            g_rank[s] = s_res;
        }
        __syncthreads();
    }
    for (int i = t; i < NBIN; i += blockDim.x) {
        g_hist[0][i] = 0u;
        g_hist[1][i] = 0u;
    }
}

// ---------------- kernels ----------------
// Zero scratch, sniff index dtype, AND build the bf16 shadow of Z.
__global__ void init_kernel(const unsigned int* __restrict__ row_words,
                            const float* __restrict__ Z) {
    int idx = blockIdx.x * blockDim.x + threadIdx.x;
    int stride = gridDim.x * blockDim.x;
    const int NZ4 = N_SAMPLES * D_FEAT / 4;
    const float4* Z4 = (const float4*)Z;
    for (int i = idx; i < NZ4; i += stride) {
        float4 v = Z4[i];
        union { __nv_bfloat162 h2[2]; uint2 u; } pk;
        pk.h2[0] = __floats2bfloat162_rn(v.x, v.y);
        pk.h2[1] = __floats2bfloat162_rn(v.z, v.w);
        g_Zh[i] = pk.u;
    }
    for (int i = idx; i < N_SAMPLES; i += stride) g_cnt[i] = 0;
    for (int i = idx; i < NBIN; i += stride) { g_hist[0][i] = 0u; g_hist[1][i] = 0u; }
    if (idx < 4) g_tick[idx] = 0u;
    if (idx == 0) {
        g_recon_sum = 0.0; g_reg_sum = 0.0; g_block_sum = 0.0;
        g_prefix[0] = 0u; g_prefix[1] = 0u;
        g_rank[0] = 799999u;   // lower-middle order statistic (0-indexed)
        g_rank[1] = 800000u;   // upper-middle
    }
    if (blockIdx.x == 0) {
        __shared__ int bad;
        if (threadIdx.x == 0) bad = 0;
        __syncthreads();
        for (int i = threadIdx.x; i < 2048; i += blockDim.x)
            if (row_words[2 * i + 1] != 0u) bad = 1;
        __syncthreads();
        if (threadIdx.x == 0) g_is64 = bad ? 0 : 1;
    }
}

// Bucket fill: slot id from the count atomic itself (no scan needed).
__global__ void fill_kernel(const void* __restrict__ rowp,
                            const void* __restrict__ colp,
                            const float* __restrict__ C) {
    int idx = blockIdx.x * blockDim.x + threadIdx.x;
    int stride = gridDim.x * blockDim.x;
    int is64 = g_is64;
    for (int e = idx; e < NUM_EDGES; e += stride) {
        int r, c;
        if (is64) {
            r = (int)((const long long*)rowp)[e];
            c = (int)((const long long*)colp)[e];
        } else {
            r = ((const int*)rowp)[e];
            c = ((const int*)colp)[e];
        }
        int slot = atomicAdd(&g_cnt[c], 1);
        if (slot < SLOT_CAP)
            g_rec[(size_t)c * SLOT_CAP + slot] = make_int4(e, r, __float_as_int(C[e]), 0);
    }
}

// Warp per column: bitonic sort by edge id, shuffle-serial ascending fp32 fold
// (bitwise = XLA-CPU sequential scatter order), packed store + nv scatter.
__global__ void percol_kernel(float* __restrict__ out) {
    int wg = (blockIdx.x * blockDim.x + threadIdx.x) >> 5;
    int lane = threadIdx.x & 31;
    if (wg >= N_SAMPLES) return;
    size_t base = (size_t)wg * SLOT_CAP;
    int n = g_cnt[wg];
    if (n > SLOT_CAP) n = SLOT_CAP;
    if (n == 0) return;
    if (n <= 32) {
        int eid = 0x7FFFFFFF, row = 0;
        float cv = 0.f;
        if (lane < n) {
            int4 r = g_rec[base + lane];
            eid = r.x; row = r.y; cv = __int_as_float(r.z);
        }
        #pragma unroll
        for (int k = 2; k <= 32; k <<= 1) {
            #pragma unroll
            for (int j = k >> 1; j > 0; j >>= 1) {
                int pe = __shfl_xor_sync(FULLMASK, eid, j);
                int pr = __shfl_xor_sync(FULLMASK, row, j);
                float pc = __shfl_xor_sync(FULLMASK, cv, j);
                bool lower = (lane & j) == 0;
                bool asc = (lane & k) == 0 || k == 32;
                bool keepSmall = (lower == asc);
                bool take = keepSmall ? (eid > pe) : (eid < pe);
                if (take) { eid = pe; row = pr; cv = pc; }
            }
        }
        float s = 0.f;
        for (int i = 0; i < n; i++)
            s = __fadd_rn(s, __shfl_sync(FULLMASK, cv, i));
        float d = __fadd_rn(s, EPS_F);
        if (lane < n) {
            float nv = __fdiv_rn(cv, d);
            Pk p; p.nv = nv; p.row = row;
            g_packed[base + lane] = p;
            out[eid] = nv;
        }
    } else if (lane == 0) {             // rare (Poisson(16) tail): serial path
        for (int i = 1; i < n; i++) {
            int4 key = g_rec[base + i];
            int j = i - 1;
            while (j >= 0 && g_rec[base + j].x > key.x) {
                g_rec[base + j + 1] = g_rec[base + j]; j--;
            }
            g_rec[base + j + 1] = key;
        }
        float s = 0.f;
        for (int i = 0; i < n; i++)
            s = __fadd_rn(s, __int_as_float(g_rec[base + i].z));
        float d = __fadd_rn(s, EPS_F);
        for (int i = 0; i < n; i++) {
            int4 r = g_rec[base + i];
            float nv = __fdiv_rn(__int_as_float(r.z), d);
            Pk p; p.nv = nv; p.row = r.y;
            g_packed[base + i] = p;
            out[r.x] = nv;
        }
    }
}

// reg_loss + 11-bit radix pass 0 (bits 30..20), plain smem atomics (proven
// faster than warp-aggregation here).
__global__ void reg_hist0_kernel(const float* __restrict__ nv_arr) {
    __shared__ unsigned int sh[NBIN];
    for (int i = threadIdx.x; i < NBIN; i += blockDim.x) sh[i] = 0u;
    __syncthreads();
    const float4* nv4 = (const float4*)nv_arr;
    int idx = blockIdx.x * blockDim.x + threadIdx.x;
    int stride = gridDim.x * blockDim.x;
    double acc = 0.0;
    for (int i = idx; i < NUM_EDGES / 4; i += stride) {
        float4 v = nv4[i];
        acc += (double)v.x * v.x + (double)v.y * v.y
             + (double)v.z * v.z + (double)v.w * v.w;
        atomicAdd(&sh[(__float_as_uint(v.x) & 0x7FFFFFFFu) >> 20], 1u);
        atomicAdd(&sh[(__float_as_uint(v.y) & 0x7FFFFFFFu) >> 20], 1u);
        atomicAdd(&sh[(__float_as_uint(v.z) & 0x7FFFFFFFu) >> 20], 1u);
        atomicAdd(&sh[(__float_as_uint(v.w) & 0x7FFFFFFFu) >> 20], 1u);
    }
    double s = blockReduceD(acc);
    __syncthreads();
    for (int i = threadIdx.x; i < NBIN; i += blockDim.x)
        if (sh[i]) atomicAdd(&g_hist[0][i], sh[i]);
    __shared__ unsigned last;
    if (threadIdx.x == 0) {
        atomicAdd(&g_reg_sum, s);
        __threadfence();
        last = atomicAdd(&g_tick[0], 1u);
    }
    __syncthreads();
    if (last == gridDim.x - 1) walk2048_and_reset(20, true);
}

// TWO warps per column (latency-bound: halve the per-warp serial chain while
// keeping registers/occupancy at the simple-loop level — R10 showed in-thread
// ILP loses more occupancy than it gains MLP). Warp sub∈{0,1} walks slots
// sub, sub+2, ...; partials merge via smem; sub==0 folds the loss.
__global__ void recon_gather_kernel(const float* __restrict__ Z) {
    int gw = (blockIdx.x * blockDim.x + threadIdx.x) >> 5;
    int col = gw >> 1;
    int sub = gw & 1;
    int lane = threadIdx.x & 31;
    int pairInBlk = threadIdx.x >> 6;          // 4 pairs per 256-thread block
    __shared__ float4 sh_acc[4][32];
    float4 acc = make_float4(0.f, 0.f, 0.f, 0.f);
    if (col < N_SAMPLES) {
        size_t base = (size_t)col * SLOT_CAP;
        int n = g_cnt[col];
        if (n > SLOT_CAP) n = SLOT_CAP;
        if (sub < n) {
            Pk p = g_packed[base + sub];
            for (int i = sub; i < n; i += 2) {
                Pk pn; pn.nv = 0.f; pn.row = 0;
                if (i + 2 < n) pn = g_packed[base + i + 2];   // prefetch
                uint2 u = g_Zh[(size_t)p.row * (D_FEAT / 4) + lane];
                union { uint2 u; __nv_bfloat162 h2[2]; } k; k.u = u;
                float2 fa = __bfloat1622float2(k.h2[0]);
                float2 fb = __bfloat1622float2(k.h2[1]);
                acc.x = fmaf(p.nv, fa.x, acc.x);
                acc.y = fmaf(p.nv, fa.y, acc.y);
                acc.z = fmaf(p.nv, fb.x, acc.z);
                acc.w = fmaf(p.nv, fb.y, acc.w);
                p = pn;
            }
        }
    }
    if (sub == 1) sh_acc[pairInBlk][lane] = acc;
    __syncthreads();
    double local = 0.0;
    if (sub == 0 && col < N_SAMPLES) {
        float4 b = sh_acc[pairInBlk][lane];
        acc.x += b.x; acc.y += b.y; acc.z += b.z; acc.w += b.w;
        const float4 zj = *reinterpret_cast<const float4*>(
            Z + (size_t)col * D_FEAT + lane * 4);
        float dx = acc.x - zj.x, dy = acc.y - zj.y;
        float dz = acc.z - zj.z, dw = acc.w - zj.w;
        local = (double)(dx * dx) + (double)(dy * dy)
              + (double)(dz * dz) + (double)(dw * dw);
    }
    double s = blockReduceD(local);
    if (threadIdx.x == 0) atomicAdd(&g_recon_sum, s);
}

// 11-bit radix pass 1 (bits 19..9) with prefix filter; last block walks.
__global__ void hist1_kernel(const float* __restrict__ nv_arr) {
    __shared__ unsigned int sh[2][NBIN];
    for (int i = threadIdx.x; i < 2 * NBIN; i += blockDim.x) (&sh[0][0])[i] = 0u;
    __syncthreads();
    unsigned p0 = g_prefix[0], p1 = g_prefix[1];
    const unsigned himask = 0xFFF00000u;
    const float4* nv4 = (const float4*)nv_arr;
    int idx = blockIdx.x * blockDim.x + threadIdx.x;
    int stride = gridDim.x * blockDim.x;
    for (int i = idx; i < NUM_EDGES / 4; i += stride) {
        float4 v = nv4[i];
        float a[4] = {v.x, v.y, v.z, v.w};
        #pragma unroll
        for (int q = 0; q < 4; q++) {
            unsigned bits = __float_as_uint(a[q]) & 0x7FFFFFFFu;
            unsigned dig = (bits >> 9) & 0x7FFu;
            unsigned hb = bits & himask;
            if (hb == p0) atomicAdd(&sh[0][dig], 1u);
            if (hb == p1) atomicAdd(&sh[1][dig], 1u);
        }
    }
    __syncthreads();
    for (int i = threadIdx.x; i < NBIN; i += blockDim.x) {
        if (sh[0][i]) atomicAdd(&g_hist[0][i], sh[0][i]);
        if (sh[1][i]) atomicAdd(&g_hist[1][i], sh[1][i]);
    }
    __shared__ unsigned last;
    if (threadIdx.x == 0) {
        __threadfence();
        last = atomicAdd(&g_tick[1], 1u);
    }
    __syncthreads();
    if (last == gridDim.x - 1) walk2048_and_reset(9, false);
}

__global__ void blockloss_finalize_kernel(const float* __restrict__ nv_arr,
                                          float* __restrict__ out, int out_size) {
    float thr = 0.5f * (__uint_as_float(g_prefix[0]) + __uint_as_float(g_prefix[1]));
    const float4* nv4 = (const float4*)nv_arr;
    int idx = blockIdx.x * blockDim.x + threadIdx.x;
    int stride = gridDim.x * blockDim.x;
    double acc = 0.0;
    for (int i = idx; i < NUM_EDGES / 4; i += stride) {
        float4 v = nv4[i];
        if (fabsf(v.x) < thr) acc += (double)v.x * v.x;
        if (fabsf(v.y) < thr) acc += (double)v.y * v.y;
        if (fabsf(v.z) < thr) acc += (double)v.z * v.z;
        if (fabsf(v.w) < thr) acc += (double)v.w * v.w;
    }
    double s = blockReduceD(acc);
    if (threadIdx.x == 0) {
        atomicAdd(&g_block_sum, s);
        __threadfence();
        unsigned t = atomicAdd(&g_tick[3], 1u);
        if (t == gridDim.x - 1 && out_size >= NUM_EDGES + 3) {
            out[NUM_EDGES + 0] =
                (float)(g_recon_sum / (double)((long long)N_SAMPLES * D_FEAT));
            out[NUM_EDGES + 1] = (float)(LAMBDA_REG * g_reg_sum);
            out[NUM_EDGES + 2] = (float)(GAMMA_C * g_block_sum);
        }
    }
}

// ---------------- launch ----------------
extern "C" void kernel_launch(void* const* d_in, const int* in_sizes, int n_in,
                              void* d_out, int out_size) {
    const float* Z    = (const float*)d_in[0];
    const float* C    = (const float*)d_in[1];
    const void*  rowp = d_in[2];
    const void*  colp = d_in[3];
    float* out = (float*)d_out;

    const int TB = 256;
    const int FB = (NUM_EDGES / 4 + TB - 1) / TB;        // 4 edges/thread
    const int WB = (N_SAMPLES * 32 + TB - 1) / TB;       // warp per column
    const int RB = (N_SAMPLES * 64 + TB - 1) / TB;       // 2 warps per column

    init_kernel<<<2048, TB>>>((const unsigned int*)rowp, Z);
    fill_kernel<<<FB, TB>>>(rowp, colp, C);
    percol_kernel<<<WB, TB>>>(out);
    reg_hist0_kernel<<<1024, TB>>>(out);
    recon_gather_kernel<<<RB, TB>>>(Z);
    hist1_kernel<<<1024, TB>>>(out);
    blockloss_finalize_kernel<<<1024, TB>>>(out, out, out_size);
}

// round 12
// speedup vs baseline: 1.1208x; 1.1208x over previous
#include <cuda_runtime.h>
#include <cstdint>

#define N_SAMPLES 100000
#define NUM_EDGES 1600000
#define D_FEAT    128
#define EPS_F     1e-8f
#define LAMBDA_REG 1.0
#define GAMMA_C    0.1
#define FULLMASK   0xFFFFFFFFu
#define SLOT_CAP   64
#define NBIN       2048

struct __align__(8) Pk { float nv; int row; };

// ---------------- device scratch (no allocations allowed) ----------------
__device__ int4         g_rec[(size_t)N_SAMPLES * SLOT_CAP];    // 102.4 MB
__device__ Pk           g_packed[(size_t)N_SAMPLES * SLOT_CAP]; // 51.2 MB
__device__ int          g_cnt[N_SAMPLES];
__device__ double       g_recon_sum;
__device__ double       g_reg_sum;
__device__ double       g_block_sum;
__device__ unsigned int g_hist[2][NBIN];
__device__ unsigned int g_prefix[2];
__device__ unsigned int g_rank[2];
__device__ unsigned int g_tick[4];
__device__ int          g_is64;

// ---------------- helpers ----------------
__device__ __forceinline__ double blockReduceD(double v) {
    __shared__ double sh[32];
    #pragma unroll
    for (int o = 16; o; o >>= 1) v += __shfl_down_sync(FULLMASK, v, o);
    int lane = threadIdx.x & 31, w = threadIdx.x >> 5;
    if (lane == 0) sh[w] = v;
    __syncthreads();
    int nw = blockDim.x >> 5;
    v = (threadIdx.x < (unsigned)nw) ? sh[threadIdx.x] : 0.0;
    if (w == 0) {
        #pragma unroll
        for (int o = 16; o; o >>= 1) v += __shfl_down_sync(FULLMASK, v, o);
    }
    return v;
}

// Block-parallel walk of the 2048-bin histograms (last block of a pass).
// Requires blockDim.x == 256.
__device__ void walk2048_and_reset(int shift, bool pass0) {
    __shared__ unsigned s_part[256];
    __shared__ unsigned s_ws[8];
    __shared__ unsigned s_found, s_res;
    int t = threadIdx.x, lane = t & 31, w = t >> 5;
    for (int s = 0; s < 2; s++) {
        const unsigned* h = pass0 ? g_hist[0] : g_hist[s];
        unsigned loc[8], psum = 0;
        #pragma unroll
        for (int q = 0; q < 8; q++) { loc[q] = h[t * 8 + q]; psum += loc[q]; }
        s_part[t] = psum;
        __syncthreads();
        unsigned v = s_part[t];
        #pragma unroll
        for (int o = 1; o < 32; o <<= 1) {
            unsigned x = __shfl_up_sync(FULLMASK, v, o);
            if (lane >= o) v += x;
        }
        if (lane == 31) s_ws[w] = v;
        __syncthreads();
        if (w == 0) {
            unsigned x = (lane < 8) ? s_ws[lane] : 0;
            #pragma unroll
            for (int o = 1; o < 8; o <<= 1) {
                unsigned y = __shfl_up_sync(FULLMASK, x, o);
                if (lane >= o) x += y;
            }
            if (lane < 8) s_ws[lane] = x;
        }
        __syncthreads();
        unsigned incl = v + (w ? s_ws[w - 1] : 0);
        unsigned cum = incl - psum;
        unsigned r = g_rank[s];
        #pragma unroll
        for (int q = 0; q < 8; q++) {
            if (cum <= r && r < cum + loc[q]) {
                s_found = (unsigned)(t * 8 + q);
                s_res = r - cum;
            }
            cum += loc[q];
        }
        __syncthreads();
        if (t == 0) {
            g_prefix[s] |= s_found << shift;
            g_rank[s] = s_res;
        }
        __syncthreads();
    }
    for (int i = t; i < NBIN; i += blockDim.x) {
        g_hist[0][i] = 0u;
        g_hist[1][i] = 0u;
    }
}

// ---------------- kernels ----------------
__global__ void init_kernel(const unsigned int* __restrict__ row_words) {
    int idx = blockIdx.x * blockDim.x + threadIdx.x;
    int stride = gridDim.x * blockDim.x;
    for (int i = idx; i < N_SAMPLES; i += stride) g_cnt[i] = 0;
    for (int i = idx; i < NBIN; i += stride) { g_hist[0][i] = 0u; g_hist[1][i] = 0u; }
    if (idx < 4) g_tick[idx] = 0u;
    if (idx == 0) {
        g_recon_sum = 0.0; g_reg_sum = 0.0; g_block_sum = 0.0;
        g_prefix[0] = 0u; g_prefix[1] = 0u;
        g_rank[0] = 799999u;   // lower-middle order statistic (0-indexed)
        g_rank[1] = 800000u;   // upper-middle
    }
    if (blockIdx.x == 0) {
        __shared__ int bad;
        if (threadIdx.x == 0) bad = 0;
        __syncthreads();
        for (int i = threadIdx.x; i < 2048; i += blockDim.x)
            if (row_words[2 * i + 1] != 0u) bad = 1;
        __syncthreads();
        if (threadIdx.x == 0) g_is64 = bad ? 0 : 1;
    }
}

// Bucket fill, 4-wide batched: gather 4 edges' metadata, issue 4 independent
// count-atomics (MLP=4 on the ~318cyc atomic return), then 4 stores.
// (R7 evidence: unbatched fill sits at 6.5% issue — pure latency exposure.)
__global__ void fill_kernel(const void* __restrict__ rowp,
                            const void* __restrict__ colp,
                            const float* __restrict__ C) {
    int tid = blockIdx.x * blockDim.x + threadIdx.x;
    int e0 = tid * 4;
    int is64 = g_is64;
    int r[4], c[4];
    float cv[4];
    int m = (e0 + 4 <= NUM_EDGES) ? 4 : (NUM_EDGES - e0 > 0 ? NUM_EDGES - e0 : 0);
    #pragma unroll
    for (int q = 0; q < 4; q++) {
        int e = e0 + q;
        if (q < m) {
            if (is64) {
                r[q] = (int)((const long long*)rowp)[e];
                c[q] = (int)((const long long*)colp)[e];
            } else {
                r[q] = ((const int*)rowp)[e];
                c[q] = ((const int*)colp)[e];
            }
            cv[q] = C[e];
        }
    }
    int slot[4];
    #pragma unroll
    for (int q = 0; q < 4; q++)
        if (q < m) slot[q] = atomicAdd(&g_cnt[c[q]], 1);
    #pragma unroll
    for (int q = 0; q < 4; q++)
        if (q < m && slot[q] < SLOT_CAP)
            g_rec[(size_t)c[q] * SLOT_CAP + slot[q]] =
                make_int4(e0 + q, r[q], __float_as_int(cv[q]), 0);
}

// Warp per column: bitonic sort by edge id, shuffle-serial ascending fp32 fold
// (bitwise = XLA-CPU sequential scatter order), packed store + nv scatter.
__global__ void percol_kernel(float* __restrict__ out) {
    int wg = (blockIdx.x * blockDim.x + threadIdx.x) >> 5;
    int lane = threadIdx.x & 31;
    if (wg >= N_SAMPLES) return;
    size_t base = (size_t)wg * SLOT_CAP;
    int n = g_cnt[wg];
    if (n > SLOT_CAP) n = SLOT_CAP;
    if (n == 0) return;
    if (n <= 32) {
        int eid = 0x7FFFFFFF, row = 0;
        float cv = 0.f;
        if (lane < n) {
            int4 r = g_rec[base + lane];
            eid = r.x; row = r.y; cv = __int_as_float(r.z);
        }
        #pragma unroll
        for (int k = 2; k <= 32; k <<= 1) {
            #pragma unroll
            for (int j = k >> 1; j > 0; j >>= 1) {
                int pe = __shfl_xor_sync(FULLMASK, eid, j);
                int pr = __shfl_xor_sync(FULLMASK, row, j);
                float pc = __shfl_xor_sync(FULLMASK, cv, j);
                bool lower = (lane & j) == 0;
                bool asc = (lane & k) == 0 || k == 32;
                bool keepSmall = (lower == asc);
                bool take = keepSmall ? (eid > pe) : (eid < pe);
                if (take) { eid = pe; row = pr; cv = pc; }
            }
        }
        float s = 0.f;
        for (int i = 0; i < n; i++)
            s = __fadd_rn(s, __shfl_sync(FULLMASK, cv, i));
        float d = __fadd_rn(s, EPS_F);
        if (lane < n) {
            float nv = __fdiv_rn(cv, d);
            Pk p; p.nv = nv; p.row = row;
            g_packed[base + lane] = p;
            out[eid] = nv;
        }
    } else if (lane == 0) {             // rare (Poisson(16) tail): serial path
        for (int i = 1; i < n; i++) {
            int4 key = g_rec[base + i];
            int j = i - 1;
            while (j >= 0 && g_rec[base + j].x > key.x) {
                g_rec[base + j + 1] = g_rec[base + j]; j--;
            }
            g_rec[base + j + 1] = key;
        }
        float s = 0.f;
        for (int i = 0; i < n; i++)
            s = __fadd_rn(s, __int_as_float(g_rec[base + i].z));
        float d = __fadd_rn(s, EPS_F);
        for (int i = 0; i < n; i++) {
            int4 r = g_rec[base + i];
            float nv = __fdiv_rn(__int_as_float(r.z), d);
            Pk p; p.nv = nv; p.row = r.y;
            g_packed[base + i] = p;
            out[r.x] = nv;
        }
    }
}

// reg_loss + 11-bit radix pass 0 (bits 30..20), plain smem atomics (proven
// faster than warp-aggregation — R9/R10 evidence).
__global__ void reg_hist0_kernel(const float* __restrict__ nv_arr) {
    __shared__ unsigned int sh[NBIN];
    for (int i = threadIdx.x; i < NBIN; i += blockDim.x) sh[i] = 0u;
    __syncthreads();
    const float4* nv4 = (const float4*)nv_arr;
    int idx = blockIdx.x * blockDim.x + threadIdx.x;
    int stride = gridDim.x * blockDim.x;
    double acc = 0.0;
    for (int i = idx; i < NUM_EDGES / 4; i += stride) {
        float4 v = nv4[i];
        acc += (double)v.x * v.x + (double)v.y * v.y
             + (double)v.z * v.z + (double)v.w * v.w;
        atomicAdd(&sh[(__float_as_uint(v.x) & 0x7FFFFFFFu) >> 20], 1u);
        atomicAdd(&sh[(__float_as_uint(v.y) & 0x7FFFFFFFu) >> 20], 1u);
        atomicAdd(&sh[(__float_as_uint(v.z) & 0x7FFFFFFFu) >> 20], 1u);
        atomicAdd(&sh[(__float_as_uint(v.w) & 0x7FFFFFFFu) >> 20], 1u);
    }
    double s = blockReduceD(acc);
    __syncthreads();
    for (int i = threadIdx.x; i < NBIN; i += blockDim.x)
        if (sh[i]) atomicAdd(&g_hist[0][i], sh[i]);
    __shared__ unsigned last;
    if (threadIdx.x == 0) {
        atomicAdd(&g_reg_sum, s);
        __threadfence();
        last = atomicAdd(&g_tick[0], 1u);
    }
    __syncthreads();
    if (last == gridDim.x - 1) walk2048_and_reset(20, true);
}

// Warp per column, simple fp32 loop — the R8 configuration. (R9-R11 evidence:
// bf16/ILP/2-warp variants all regress; cross-column occupancy already hides
// the chain latency.)
__global__ void recon_gather_kernel(const float* __restrict__ Z) {
    int wg = (blockIdx.x * blockDim.x + threadIdx.x) >> 5;
    int lane = threadIdx.x & 31;
    double local = 0.0;
    if (wg < N_SAMPLES) {
        size_t base = (size_t)wg * SLOT_CAP;
        int n = g_cnt[wg];
        if (n > SLOT_CAP) n = SLOT_CAP;
        float4 acc = make_float4(0.f, 0.f, 0.f, 0.f);
        if (n > 0) {
            Pk p = g_packed[base];
            for (int i = 0; i < n; i++) {
                Pk pn; pn.nv = 0.f; pn.row = 0;
                if (i + 1 < n) pn = g_packed[base + i + 1];   // prefetch
                const float4 z = *reinterpret_cast<const float4*>(
                    Z + (size_t)p.row * D_FEAT + lane * 4);
                acc.x = fmaf(p.nv, z.x, acc.x);
                acc.y = fmaf(p.nv, z.y, acc.y);
                acc.z = fmaf(p.nv, z.z, acc.z);
                acc.w = fmaf(p.nv, z.w, acc.w);
                p = pn;
            }
        }
        const float4 zj = *reinterpret_cast<const float4*>(
            Z + (size_t)wg * D_FEAT + lane * 4);
        float dx = acc.x - zj.x, dy = acc.y - zj.y;
        float dz = acc.z - zj.z, dw = acc.w - zj.w;
        local = (double)(dx * dx) + (double)(dy * dy)
              + (double)(dz * dz) + (double)(dw * dw);
    }
    double s = blockReduceD(local);
    if (threadIdx.x == 0) atomicAdd(&g_recon_sum, s);
}

// 11-bit radix pass 1 (bits 19..9) with prefix filter; last block walks.
__global__ void hist1_kernel(const float* __restrict__ nv_arr) {
    __shared__ unsigned int sh[2][NBIN];
    for (int i = threadIdx.x; i < 2 * NBIN; i += blockDim.x) (&sh[0][0])[i] = 0u;
    __syncthreads();
    unsigned p0 = g_prefix[0], p1 = g_prefix[1];
    const unsigned himask = 0xFFF00000u;
    const float4* nv4 = (const float4*)nv_arr;
    int idx = blockIdx.x * blockDim.x + threadIdx.x;
    int stride = gridDim.x * blockDim.x;
    for (int i = idx; i < NUM_EDGES / 4; i += stride) {
        float4 v = nv4[i];
        float a[4] = {v.x, v.y, v.z, v.w};
        #pragma unroll
        for (int q = 0; q < 4; q++) {
            unsigned bits = __float_as_uint(a[q]) & 0x7FFFFFFFu;
            unsigned dig = (bits >> 9) & 0x7FFu;
            unsigned hb = bits & himask;
            if (hb == p0) atomicAdd(&sh[0][dig], 1u);
            if (hb == p1) atomicAdd(&sh[1][dig], 1u);
        }
    }
    __syncthreads();
    for (int i = threadIdx.x; i < NBIN; i += blockDim.x) {
        if (sh[0][i]) atomicAdd(&g_hist[0][i], sh[0][i]);
        if (sh[1][i]) atomicAdd(&g_hist[1][i], sh[1][i]);
    }
    __shared__ unsigned last;
    if (threadIdx.x == 0) {
        __threadfence();
        last = atomicAdd(&g_tick[1], 1u);
    }
    __syncthreads();
    if (last == gridDim.x - 1) walk2048_and_reset(9, false);
}

__global__ void blockloss_finalize_kernel(const float* __restrict__ nv_arr,
                                          float* __restrict__ out, int out_size) {
    float thr = 0.5f * (__uint_as_float(g_prefix[0]) + __uint_as_float(g_prefix[1]));
    const float4* nv4 = (const float4*)nv_arr;
    int idx = blockIdx.x * blockDim.x + threadIdx.x;
    int stride = gridDim.x * blockDim.x;
    double acc = 0.0;
    for (int i = idx; i < NUM_EDGES / 4; i += stride) {
        float4 v = nv4[i];
        if (fabsf(v.x) < thr) acc += (double)v.x * v.x;
        if (fabsf(v.y) < thr) acc += (double)v.y * v.y;
        if (fabsf(v.z) < thr) acc += (double)v.z * v.z;
        if (fabsf(v.w) < thr) acc += (double)v.w * v.w;
    }
    double s = blockReduceD(acc);
    if (threadIdx.x == 0) {
        atomicAdd(&g_block_sum, s);
        __threadfence();
        unsigned t = atomicAdd(&g_tick[3], 1u);
        if (t == gridDim.x - 1 && out_size >= NUM_EDGES + 3) {
            out[NUM_EDGES + 0] =
                (float)(g_recon_sum / (double)((long long)N_SAMPLES * D_FEAT));
            out[NUM_EDGES + 1] = (float)(LAMBDA_REG * g_reg_sum);
            out[NUM_EDGES + 2] = (float)(GAMMA_C * g_block_sum);
        }
    }
}

// ---------------- launch ----------------
extern "C" void kernel_launch(void* const* d_in, const int* in_sizes, int n_in,
                              void* d_out, int out_size) {
    const float* Z    = (const float*)d_in[0];
    const float* C    = (const float*)d_in[1];
    const void*  rowp = d_in[2];
    const void*  colp = d_in[3];
    float* out = (float*)d_out;

    const int TB = 256;
    const int FB = (NUM_EDGES / 4 + TB - 1) / TB;        // 4 edges/thread, batched
    const int WB = (N_SAMPLES * 32 + TB - 1) / TB;       // warp per column

    init_kernel<<<512, TB>>>((const unsigned int*)rowp);
    fill_kernel<<<FB, TB>>>(rowp, colp, C);
    percol_kernel<<<WB, TB>>>(out);
    reg_hist0_kernel<<<1024, TB>>>(out);
    recon_gather_kernel<<<WB, TB>>>(Z);
    hist1_kernel<<<1024, TB>>>(out);
    blockloss_finalize_kernel<<<1024, TB>>>(out, out, out_size);
}